// round 15
// baseline (speedup 1.0000x reference)
#include <cuda_runtime.h>
#include <cuda_fp16.h>
#include <cstdint>

#define B 4
#define L 4096
#define W 2048
#define H 8
#define BW 256
#define M_ROWS (B*L)   // 16384
#define NC 64          // scan chunks
#define CHUNK (L/NC)   // 64

// ---------------- device scratch (no allocs allowed) ----------------
__device__ __half g_wF[2][H * BW * BW];             // [gate][h][n][k]  fp16
__device__ float g_sp[W];                           // softplus(a_param)
__device__ float g_axn[(size_t)2 * M_ROWS * W];     // interleaved (a_eff, x_norm)
__device__ float2 g_Ph [NC * B * W];                // per-chunk (P, h_end)
__device__ float  g_cin[NC * B * W];                // per-chunk carry-in

// ---------------- PTX helpers ----------------
__device__ __forceinline__ uint32_t smem_u32(const void* p) {
    uint32_t a;
    asm("{ .reg .u64 t; cvta.to.shared.u64 t, %1; cvt.u32.u64 %0, t; }" : "=r"(a) : "l"(p));
    return a;
}
#define CP16(dst, src) \
    asm volatile("cp.async.cg.shared.global [%0], [%1], 16;" :: "r"(dst), "l"(src))
#define CP_COMMIT() asm volatile("cp.async.commit_group;" ::: "memory")
#define CP_WAIT(n)  asm volatile("cp.async.wait_group %0;" :: "n"(n) : "memory")

__device__ __forceinline__ void ldsm4(uint32_t* r, uint32_t addr) {
    asm volatile("ldmatrix.sync.aligned.m8n8.x4.shared.b16 {%0,%1,%2,%3}, [%4];"
                 : "=r"(r[0]), "=r"(r[1]), "=r"(r[2]), "=r"(r[3]) : "r"(addr));
}
__device__ __forceinline__ void mma16816(float* c, const uint32_t* a, const uint32_t* b) {
    asm volatile("mma.sync.aligned.m16n8k16.row.col.f32.f16.f16.f32 "
                 "{%0,%1,%2,%3}, {%4,%5,%6,%7}, {%8,%9}, {%0,%1,%2,%3};"
                 : "+f"(c[0]), "+f"(c[1]), "+f"(c[2]), "+f"(c[3])
                 : "r"(a[0]), "r"(a[1]), "r"(a[2]), "r"(a[3]), "r"(b[0]), "r"(b[1]));
}
__device__ __forceinline__ void pack4h(const float4 v, uint32_t& p01, uint32_t& p23) {
    __half2 a = __halves2half2(__float2half(v.x), __float2half(v.y));
    __half2 b = __halves2half2(__float2half(v.z), __float2half(v.w));
    p01 = *(uint32_t*)&a; p23 = *(uint32_t*)&b;
}

// ---------------- K0: transpose w -> fp16 [n][k] (one gate per launch) --------
__global__ void convert_w_kernel(const float* __restrict__ wsrc, int g) {
    int hd = blockIdx.x, z = blockIdx.y;
    const float* src = wsrc + (size_t)hd * BW * BW + z * 8192;
    for (int e = threadIdx.x; e < 8192; e += 256) {
        int ee = z * 8192 + e;
        int i = ee >> 8, j = ee & 255;  // src[i=k][j=n]
        g_wF[g][(size_t)hd * BW * BW + (size_t)j * BW + i] = __float2half(src[e]);
    }
}

// ---------------- K0c: softplus(a_param) ----------------
__global__ void sp_kernel(const float* __restrict__ a_param) {
    int i = blockIdx.x * 256 + threadIdx.x;
    g_sp[i] = log1pf(__expf(a_param[i]));
}

// ---------------- K1: mma.sync dual-gate GEMM + fused epilogue + local scan ---
// Block: 64 rows x 256 cols (one full head), both gates, K=256 in 4 chunks of 64.
// 1024 threads: 32 warps as 2(M)x16(N16), warp tile 32x16 PER GATE.
// acc = 32 regs/thread; 1 block/SM = 32 warps/SM. A converted f32->fp16 in-kernel.
#define ROWB 144                          // smem row stride bytes (64 halves + pad)
#define A_BYTES (64 * ROWB)               // 9216
#define B_BYTES (256 * ROWB)              // 36864
#define BOFF(g_) (A_BYTES + (g_) * B_BYTES)
#define STAGE_B (A_BYTES + 2 * B_BYTES)   // 82944
#define SSTRIDE 258                       // scan buffer stride (float2 units)
#define SMEM_TOTAL (2 * STAGE_B)          // 165888 >= 64*SSTRIDE*8 (132096)

__global__ void __launch_bounds__(1024, 1)
gemm_fused_kernel(const float* __restrict__ x,
                  const int* __restrict__ segpos,
                  const float* __restrict__ ig_b,
                  const float* __restrict__ ag_b)
{
    extern __shared__ char smem[];
    const uint32_t sm0 = smem_u32(smem);

    const int tid = threadIdx.x;
    const int wid = tid >> 5;
    const int lane = tid & 31;
    const int m0 = blockIdx.x * 64;
    const int hd = blockIdx.y;
    const int warpM = (wid & 1) * 32;
    const int warpN = (wid >> 1) * 16;

    // A f32 source: thread owns row = tid>>4, 4 consecutive k at (tid&15)*4
    const int arow = tid >> 4;
    const int aseg = (tid & 15) * 4;
    const float* asrc = x + (size_t)(m0 + arow) * W + hd * BW + aseg;
    const uint32_t asts = arow * ROWB + aseg * 2;

    float4 areg;
    auto ldg_A = [&](int kc) { areg = __ldg((const float4*)(asrc + kc * 64)); };
    auto sts_A = [&](uint32_t sb) {
        uint32_t p0, p1;
        pack4h(areg, p0, p1);
        asm volatile("st.shared.v2.b32 [%0], {%1,%2};"
                     :: "r"(sb + asts), "r"(p0), "r"(p1));
    };
    auto cp_B = [&](int kc, uint32_t sb) {
        int kcol = kc * 64;
#pragma unroll
        for (int g = 0; g < 2; g++) {
            const __half* sB = g_wF[g] + (size_t)hd * BW * BW + kcol;
            uint32_t db = sb + BOFF(g);
#pragma unroll
            for (int it = 0; it < 2; it++) {
                int i = it * 1024 + tid;
                int n = i >> 3, q = i & 7;
                CP16(db + n * ROWB + q * 16, sB + (size_t)n * BW + q * 8);
            }
        }
    };

    const uint32_t a_lane = (uint32_t)((warpM + (lane & 7) + ((lane >> 3) & 1) * 8) * ROWB
                                       + (lane >> 4) * 16);
    const uint32_t b_lane = (uint32_t)((warpN + (lane & 7) + ((lane >> 4) & 1) * 8) * ROWB
                                       + ((lane >> 3) & 1) * 16);

    float acc[2][2][2][4];   // [gate][mt][nt][e] = 32 regs
#pragma unroll
    for (int g = 0; g < 2; g++)
#pragma unroll
        for (int mt = 0; mt < 2; mt++)
#pragma unroll
            for (int nt = 0; nt < 2; nt++)
#pragma unroll
                for (int e = 0; e < 4; e++) acc[g][mt][nt][e] = 0.f;

    ldg_A(0);
    sts_A(sm0);
    cp_B(0, sm0);
    CP_COMMIT();

#pragma unroll 1
    for (int kc = 0; kc < 4; kc++) {
        uint32_t cur = sm0 + (kc & 1) * STAGE_B;
        uint32_t nxt = sm0 + ((kc + 1) & 1) * STAGE_B;
        if (kc < 3) { cp_B(kc + 1, nxt); CP_COMMIT(); ldg_A(kc + 1); }
        if (kc < 3) CP_WAIT(1); else CP_WAIT(0);
        __syncthreads();

#pragma unroll
        for (int ks = 0; ks < 4; ks++) {
            uint32_t ka = ks * 32;
            uint32_t a0[4], a1[4];
            ldsm4(a0, cur + a_lane + ka);
            ldsm4(a1, cur + a_lane + 16 * ROWB + ka);
#pragma unroll
            for (int g = 0; g < 2; g++) {
                uint32_t bb[4];        // n16 x k16 for this gate
                ldsm4(bb, cur + BOFF(g) + b_lane + ka);
                mma16816(acc[g][0][0], a0, bb);
                mma16816(acc[g][0][1], a0, bb + 2);
                mma16816(acc[g][1][0], a1, bb);
                mma16816(acc[g][1][1], a1, bb + 2);
            }
        }
        if (kc < 3) sts_A(nxt);
        __syncthreads();
    }

    // ---- fused epilogue: column params hoisted; x f32 (L2-hot) ----
    float2* s_scan = (float2*)smem;   // [64 rows][SSTRIDE cols]
    float bis[2][2], bas[2][2], sps[2][2];
#pragma unroll
    for (int nt = 0; nt < 2; nt++) {
        int nglob = hd * BW + warpN + nt * 8 + (lane & 3) * 2;
        float2 v;
        v = __ldg((const float2*)(ig_b + nglob)); bis[nt][0] = v.x; bis[nt][1] = v.y;
        v = __ldg((const float2*)(ag_b + nglob)); bas[nt][0] = v.x; bas[nt][1] = v.y;
        v = __ldg((const float2*)(g_sp + nglob)); sps[nt][0] = v.x; sps[nt][1] = v.y;
    }
#pragma unroll
    for (int mt = 0; mt < 2; mt++) {
#pragma unroll
        for (int half = 0; half < 2; half++) {
            int lrow = warpM + mt * 16 + half * 8 + (lane >> 2);
            int m = m0 + lrow;
            bool reset = (__ldg(&segpos[m & (L - 1)]) == 0);
#pragma unroll
            for (int nt = 0; nt < 2; nt++) {
                int lcol = warpN + nt * 8 + (lane & 3) * 2;
                int nglob = hd * BW + lcol;
                float2 xv = *(const float2*)(x + (size_t)m * W + nglob);
                float xs[2] = {xv.x, xv.y};
                float res[4];
#pragma unroll
                for (int j = 0; j < 2; j++) {
                    float pi = acc[0][mt][nt][half * 2 + j] + bis[nt][j];
                    float pa = acc[1][mt][nt][half * 2 + j] + bas[nt][j];
                    float gx = __fdividef(1.f, 1.f + __expf(-pi));
                    float sa = __fdividef(1.f, 1.f + __expf(-pa));
                    float a = __expf(-8.f * sa * sps[nt][j]);
                    float mult = reset ? 1.f : sqrtf(fmaxf(1.f - a * a, 0.f));
                    res[j * 2 + 0] = reset ? 0.f : a;          // a_eff
                    res[j * 2 + 1] = xs[j] * gx * mult;        // x_norm
                }
                float4 pk = make_float4(res[0], res[1], res[2], res[3]);
                *(float4*)(g_axn + ((size_t)m * W + nglob) * 2) = pk;
                *(float4*)&s_scan[lrow * SSTRIDE + lcol] = pk;
            }
        }
    }
    __syncthreads();

    // ---- chunk-local scan: one chunk (64 rows) x 256 channels ----
    if (tid < 256) {
        int j = tid;
        float P = 1.f, h = 0.f;
#pragma unroll 8
        for (int t = 0; t < CHUNK; t++) {
            float2 v = s_scan[t * SSTRIDE + j];
            h = fmaf(v.x, h, v.y);
            P *= v.x;
        }
        int b_idx = m0 >> 12;
        int cglob = (m0 & (L - 1)) >> 6;
        int w = hd * BW + j;
        g_Ph[(cglob * B + b_idx) * W + w] = make_float2(P, h);
    }
}

// ---------------- K3: sequential carry combine + last_h ----------------
__global__ void carry_kernel(const float* __restrict__ prev_h,
                             float* __restrict__ out, int out_size) {
    int t = blockIdx.x * 256 + threadIdx.x;   // 0 .. B*W-1
    if (t >= B * W) return;
    int b = t / W, w = t % W;
    float carry = prev_h[t];
#pragma unroll 16
    for (int c = 0; c < NC; c++) {
        int s = (c * B + b) * W + w;
        float2 ph = __ldg(&g_Ph[s]);
        g_cin[s] = carry;
        carry = fmaf(ph.x, carry, ph.y);
    }
    if (out_size >= (int)((size_t)B * L * W + B * W))
        out[(size_t)B * L * W + t] = carry;
}

// ---------------- K4: finalize — rescan with carry-in, write y (2 ch/thread) --
__global__ void __launch_bounds__(256)
finalize_kernel(float* __restrict__ out) {
    const int w2 = (blockIdx.x * 256 + threadIdx.x) * 2;
    const int b = blockIdx.y;
    const int c = blockIdx.z;
    const float4* p4 = (const float4*)g_axn;
    size_t rowbase = ((size_t)b * L + c * CHUNK) * W;

    int cb = (c * B + b) * W + w2;
    float h0 = g_cin[cb], h1 = g_cin[cb + 1];
#pragma unroll 8
    for (int t = 0; t < CHUNK; t++) {
        size_t idx = rowbase + (size_t)t * W + w2;
        float4 v = __ldg(&p4[idx >> 1]);
        h0 = fmaf(v.x, h0, v.y);
        h1 = fmaf(v.z, h1, v.w);
        *(float2*)(out + idx) = make_float2(h0, h1);
    }
}

// ---------------- launcher ----------------
extern "C" void kernel_launch(void* const* d_in, const int* in_sizes, int n_in,
                              void* d_out, int out_size)
{
    const float* x       = (const float*)d_in[0];
    const int*   segpos  = (const int*)  d_in[1];
    const float* prev_h  = (const float*)d_in[2];
    const float* ig_w    = (const float*)d_in[3];
    const float* ig_b    = (const float*)d_in[4];
    const float* ag_w    = (const float*)d_in[5];
    const float* ag_b    = (const float*)d_in[6];
    const float* a_param = (const float*)d_in[7];
    float* out = (float*)d_out;

    cudaFuncSetAttribute(gemm_fused_kernel,
                         cudaFuncAttributeMaxDynamicSharedMemorySize, SMEM_TOTAL);

    // launches 1-3 (small); gemm stays 4th -> lands in the ncu capture window
    convert_w_kernel<<<dim3(H, 8), 256>>>(ig_w, 0);
    convert_w_kernel<<<dim3(H, 8), 256>>>(ag_w, 1);
    sp_kernel<<<W / 256, 256>>>(a_param);

    gemm_fused_kernel<<<dim3(M_ROWS / 64, H), 1024, SMEM_TOTAL>>>(
        x, segpos, ig_b, ag_b);

    carry_kernel<<<(B * W + 255) / 256, 256>>>(prev_h, out, out_size);
    finalize_kernel<<<dim3(W / 512, B, NC), 256>>>(out);
}

// round 16
// speedup vs baseline: 1.4402x; 1.4402x over previous
#include <cuda_runtime.h>
#include <cuda_fp16.h>
#include <cstdint>

#define B 4
#define L 4096
#define W 2048
#define H 8
#define BW 256
#define M_ROWS (B*L)   // 16384
#define NC 64          // scan chunks
#define CHUNK (L/NC)   // 64

// ---------------- device scratch (no allocs allowed) ----------------
__device__ __half g_wF[2][H * BW * BW];             // [gate][h][n][k]  fp16
__device__ float g_sp[W];                           // softplus(a_param)
__device__ float g_axn[(size_t)2 * M_ROWS * W];     // interleaved (a_eff, x_norm)
__device__ float2 g_Ph [NC * B * W];                // per-chunk (P, h_end)
__device__ float  g_cin[NC * B * W];                // per-chunk carry-in

// ---------------- PTX helpers ----------------
__device__ __forceinline__ uint32_t smem_u32(const void* p) {
    uint32_t a;
    asm("{ .reg .u64 t; cvta.to.shared.u64 t, %1; cvt.u32.u64 %0, t; }" : "=r"(a) : "l"(p));
    return a;
}
#define CP16(dst, src) \
    asm volatile("cp.async.cg.shared.global [%0], [%1], 16;" :: "r"(dst), "l"(src))
#define CP_COMMIT() asm volatile("cp.async.commit_group;" ::: "memory")
#define CP_WAIT(n)  asm volatile("cp.async.wait_group %0;" :: "n"(n) : "memory")

__device__ __forceinline__ void ldsm4(uint32_t* r, uint32_t addr) {
    asm volatile("ldmatrix.sync.aligned.m8n8.x4.shared.b16 {%0,%1,%2,%3}, [%4];"
                 : "=r"(r[0]), "=r"(r[1]), "=r"(r[2]), "=r"(r[3]) : "r"(addr));
}
__device__ __forceinline__ void mma16816(float* c, const uint32_t* a, const uint32_t* b) {
    asm volatile("mma.sync.aligned.m16n8k16.row.col.f32.f16.f16.f32 "
                 "{%0,%1,%2,%3}, {%4,%5,%6,%7}, {%8,%9}, {%0,%1,%2,%3};"
                 : "+f"(c[0]), "+f"(c[1]), "+f"(c[2]), "+f"(c[3])
                 : "r"(a[0]), "r"(a[1]), "r"(a[2]), "r"(a[3]), "r"(b[0]), "r"(b[1]));
}
__device__ __forceinline__ void pack4h(const float4 v, uint32_t& p01, uint32_t& p23) {
    __half2 a = __halves2half2(__float2half(v.x), __float2half(v.y));
    __half2 b = __halves2half2(__float2half(v.z), __float2half(v.w));
    p01 = *(uint32_t*)&a; p23 = *(uint32_t*)&b;
}

// ---------------- K0: transpose w -> fp16 [n][k] (one gate per launch) --------
__global__ void convert_w_kernel(const float* __restrict__ wsrc, int g) {
    int hd = blockIdx.x, z = blockIdx.y;
    const float* src = wsrc + (size_t)hd * BW * BW + z * 8192;
    for (int e = threadIdx.x; e < 8192; e += 256) {
        int ee = z * 8192 + e;
        int i = ee >> 8, j = ee & 255;  // src[i=k][j=n]
        g_wF[g][(size_t)hd * BW * BW + (size_t)j * BW + i] = __float2half(src[e]);
    }
}

// ---------------- K0c: softplus(a_param) ----------------
__global__ void sp_kernel(const float* __restrict__ a_param) {
    int i = blockIdx.x * 256 + threadIdx.x;
    g_sp[i] = log1pf(__expf(a_param[i]));
}

// ---------------- K1: mma.sync dual-gate GEMM + fused epilogue + local scan ---
// Block: 64 rows x 128 cols, both gates, K=256 in 4 chunks of 64.
// 512 threads: 16 warps as 2(M)x8(N16), warp tile 32x16 PER GATE.
// acc = 32 regs; 2 blocks/SM = 32 warps/SM. A converted f32->fp16 in-kernel.
#define ROWB 144                       // smem row stride bytes (64 halves + pad)
#define A_BYTES (64 * ROWB)            // 9216
#define B_BYTES (128 * ROWB)           // 18432
#define BOFF(g_) (A_BYTES + (g_) * B_BYTES)
#define STAGE_B (A_BYTES + 2 * B_BYTES)   // 46080
#define SSTRIDE 130                    // scan buffer stride (float2 units)
#define SMEM_TOTAL (2 * STAGE_B)       // 92160 >= 64*SSTRIDE*8 (66560)

__global__ void __launch_bounds__(512, 2)
gemm_fused_kernel(const float* __restrict__ x,
                  const int* __restrict__ segpos,
                  const float* __restrict__ ig_b,
                  const float* __restrict__ ag_b)
{
    extern __shared__ char smem[];
    const uint32_t sm0 = smem_u32(smem);

    const int tid = threadIdx.x;
    const int wid = tid >> 5;
    const int lane = tid & 31;
    const int m0 = blockIdx.x * 64;
    const int hd = blockIdx.y;
    const int nbase = blockIdx.z * 128;
    const int warpM = (wid & 1) * 32;
    const int warpN = (wid >> 1) * 16;

    // A f32 source: thread owns row = tid>>3, 8 k-floats at (tid&7)*8
    const int arow = tid >> 3;
    const int aseg = (tid & 7) * 8;
    const float* asrc = x + (size_t)(m0 + arow) * W + hd * BW + aseg;
    const uint32_t asts = arow * ROWB + aseg * 2;

    float4 areg[2];
    auto ldg_A = [&](int kc) {
        const float4* p = (const float4*)(asrc + kc * 64);
        areg[0] = __ldg(p); areg[1] = __ldg(p + 1);
    };
    auto sts_A = [&](uint32_t sb) {
        uint32_t p0, p1, p2, p3;
        pack4h(areg[0], p0, p1);
        pack4h(areg[1], p2, p3);
        asm volatile("st.shared.v4.b32 [%0], {%1,%2,%3,%4};"
                     :: "r"(sb + asts), "r"(p0), "r"(p1), "r"(p2), "r"(p3));
    };
    auto cp_B = [&](int kc, uint32_t sb) {
        int kcol = kc * 64;
#pragma unroll
        for (int g = 0; g < 2; g++) {
            const __half* sB = g_wF[g] + (size_t)hd * BW * BW + (size_t)nbase * BW + kcol;
            uint32_t db = sb + BOFF(g);
#pragma unroll
            for (int it = 0; it < 2; it++) {
                int i = it * 512 + tid;
                int n = i >> 3, q = i & 7;
                CP16(db + n * ROWB + q * 16, sB + (size_t)n * BW + q * 8);
            }
        }
    };

    const uint32_t a_lane = (uint32_t)((warpM + (lane & 7) + ((lane >> 3) & 1) * 8) * ROWB
                                       + (lane >> 4) * 16);
    const uint32_t b_lane = (uint32_t)((warpN + (lane & 7) + ((lane >> 4) & 1) * 8) * ROWB
                                       + ((lane >> 3) & 1) * 16);

    float acc[2][2][2][4];   // [gate][mt][nt][e] = 32 regs
#pragma unroll
    for (int g = 0; g < 2; g++)
#pragma unroll
        for (int mt = 0; mt < 2; mt++)
#pragma unroll
            for (int nt = 0; nt < 2; nt++)
#pragma unroll
                for (int e = 0; e < 4; e++) acc[g][mt][nt][e] = 0.f;

    ldg_A(0);
    sts_A(sm0);
    cp_B(0, sm0);
    CP_COMMIT();

#pragma unroll 1
    for (int kc = 0; kc < 4; kc++) {
        uint32_t cur = sm0 + (kc & 1) * STAGE_B;
        uint32_t nxt = sm0 + ((kc + 1) & 1) * STAGE_B;
        if (kc < 3) { cp_B(kc + 1, nxt); CP_COMMIT(); ldg_A(kc + 1); }
        if (kc < 3) CP_WAIT(1); else CP_WAIT(0);
        __syncthreads();

#pragma unroll
        for (int ks = 0; ks < 4; ks++) {
            uint32_t ka = ks * 32;
            uint32_t a0[4], a1[4];
            ldsm4(a0, cur + a_lane + ka);
            ldsm4(a1, cur + a_lane + 16 * ROWB + ka);
#pragma unroll
            for (int g = 0; g < 2; g++) {
                uint32_t bb[4];        // n16 x k16 for this gate
                ldsm4(bb, cur + BOFF(g) + b_lane + ka);
                mma16816(acc[g][0][0], a0, bb);
                mma16816(acc[g][0][1], a0, bb + 2);
                mma16816(acc[g][1][0], a1, bb);
                mma16816(acc[g][1][1], a1, bb + 2);
            }
        }
        if (kc < 3) sts_A(nxt);
        __syncthreads();
    }

    // ---- fused epilogue: column params hoisted; x f32 (L2-hot from mainloop) --
    float2* s_scan = (float2*)smem;   // [64 rows][SSTRIDE cols]
    float bis[2][2], bas[2][2], sps[2][2];
#pragma unroll
    for (int nt = 0; nt < 2; nt++) {
        int nglob = hd * BW + nbase + warpN + nt * 8 + (lane & 3) * 2;
        float2 v;
        v = __ldg((const float2*)(ig_b + nglob)); bis[nt][0] = v.x; bis[nt][1] = v.y;
        v = __ldg((const float2*)(ag_b + nglob)); bas[nt][0] = v.x; bas[nt][1] = v.y;
        v = __ldg((const float2*)(g_sp + nglob)); sps[nt][0] = v.x; sps[nt][1] = v.y;
    }
#pragma unroll
    for (int mt = 0; mt < 2; mt++) {
#pragma unroll
        for (int half = 0; half < 2; half++) {
            int lrow = warpM + mt * 16 + half * 8 + (lane >> 2);
            int m = m0 + lrow;
            bool reset = (__ldg(&segpos[m & (L - 1)]) == 0);
#pragma unroll
            for (int nt = 0; nt < 2; nt++) {
                int lcol = warpN + nt * 8 + (lane & 3) * 2;
                int nglob = hd * BW + nbase + lcol;
                float2 xv = *(const float2*)(x + (size_t)m * W + nglob);
                float xs[2] = {xv.x, xv.y};
                float res[4];
#pragma unroll
                for (int j = 0; j < 2; j++) {
                    float pi = acc[0][mt][nt][half * 2 + j] + bis[nt][j];
                    float pa = acc[1][mt][nt][half * 2 + j] + bas[nt][j];
                    float gx = __fdividef(1.f, 1.f + __expf(-pi));
                    float sa = __fdividef(1.f, 1.f + __expf(-pa));
                    float a = __expf(-8.f * sa * sps[nt][j]);
                    float mult = reset ? 1.f : sqrtf(fmaxf(1.f - a * a, 0.f));
                    res[j * 2 + 0] = reset ? 0.f : a;          // a_eff
                    res[j * 2 + 1] = xs[j] * gx * mult;        // x_norm
                }
                float4 pk = make_float4(res[0], res[1], res[2], res[3]);
                *(float4*)(g_axn + ((size_t)m * W + nglob) * 2) = pk;
                *(float4*)&s_scan[lrow * SSTRIDE + lcol] = pk;
            }
        }
    }
    __syncthreads();

    // ---- chunk-local scan: this block holds exactly ONE chunk (64 rows) ----
    if (tid < 128) {
        int j = tid;
        float P = 1.f, h = 0.f;
#pragma unroll 8
        for (int t = 0; t < CHUNK; t++) {
            float2 v = s_scan[t * SSTRIDE + j];
            h = fmaf(v.x, h, v.y);
            P *= v.x;
        }
        int b_idx = m0 >> 12;
        int cglob = (m0 & (L - 1)) >> 6;
        int w = hd * BW + nbase + j;
        g_Ph[(cglob * B + b_idx) * W + w] = make_float2(P, h);
    }
}

// ---------------- K3: sequential carry combine + last_h ----------------
__global__ void carry_kernel(const float* __restrict__ prev_h,
                             float* __restrict__ out, int out_size) {
    int t = blockIdx.x * 256 + threadIdx.x;   // 0 .. B*W-1
    if (t >= B * W) return;
    int b = t / W, w = t % W;
    float carry = prev_h[t];
#pragma unroll 16
    for (int c = 0; c < NC; c++) {
        int s = (c * B + b) * W + w;
        float2 ph = __ldg(&g_Ph[s]);
        g_cin[s] = carry;
        carry = fmaf(ph.x, carry, ph.y);
    }
    if (out_size >= (int)((size_t)B * L * W + B * W))
        out[(size_t)B * L * W + t] = carry;
}

// ---------------- K4: finalize — rescan with carry-in, write y (2 ch/thread) --
__global__ void __launch_bounds__(256)
finalize_kernel(float* __restrict__ out) {
    const int w2 = (blockIdx.x * 256 + threadIdx.x) * 2;
    const int b = blockIdx.y;
    const int c = blockIdx.z;
    const float4* p4 = (const float4*)g_axn;
    size_t rowbase = ((size_t)b * L + c * CHUNK) * W;

    int cb = (c * B + b) * W + w2;
    float h0 = g_cin[cb], h1 = g_cin[cb + 1];
#pragma unroll 8
    for (int t = 0; t < CHUNK; t++) {
        size_t idx = rowbase + (size_t)t * W + w2;
        float4 v = __ldg(&p4[idx >> 1]);
        h0 = fmaf(v.x, h0, v.y);
        h1 = fmaf(v.z, h1, v.w);
        *(float2*)(out + idx) = make_float2(h0, h1);
    }
}

// ---------------- launcher ----------------
extern "C" void kernel_launch(void* const* d_in, const int* in_sizes, int n_in,
                              void* d_out, int out_size)
{
    const float* x       = (const float*)d_in[0];
    const int*   segpos  = (const int*)  d_in[1];
    const float* prev_h  = (const float*)d_in[2];
    const float* ig_w    = (const float*)d_in[3];
    const float* ig_b    = (const float*)d_in[4];
    const float* ag_w    = (const float*)d_in[5];
    const float* ag_b    = (const float*)d_in[6];
    const float* a_param = (const float*)d_in[7];
    float* out = (float*)d_out;

    cudaFuncSetAttribute(gemm_fused_kernel,
                         cudaFuncAttributeMaxDynamicSharedMemorySize, SMEM_TOTAL);

    // launches 1-3 (small); gemm stays 4th -> lands in the ncu capture window
    convert_w_kernel<<<dim3(H, 8), 256>>>(ig_w, 0);
    convert_w_kernel<<<dim3(H, 8), 256>>>(ag_w, 1);
    sp_kernel<<<W / 256, 256>>>(a_param);

    gemm_fused_kernel<<<dim3(M_ROWS / 64, H, 2), 512, SMEM_TOTAL>>>(
        x, segpos, ig_b, ag_b);

    carry_kernel<<<(B * W + 255) / 256, 256>>>(prev_h, out, out_size);
    finalize_kernel<<<dim3(W / 512, B, NC), 256>>>(out);
}